// round 13
// baseline (speedup 1.0000x reference)
#include <cuda_runtime.h>
#include <cuda_fp16.h>

#define TW 2048
#define WA 49
#define NQ (TW*WA)
#define NKV (3*TW*WA)
#define CIN 512
#define D 256
#define SCALE_F 0.17677669529663687f

__device__ __half gWq_h[D*CIN];
__device__ __half gWkv_h[2*D*CIN];
__device__ __half gWp_h[D*D];
__device__ __half gQh[(size_t)NQ*D];
__device__ __half gK[(size_t)NKV*D], gV[(size_t)NKV*D];
__device__ float  gO[(size_t)NQ*D];

__device__ __forceinline__ void fsplit(float v, __half& hi, __half& lo){
    hi = __float2half_rn(v);
    lo = __float2half_rn(v - __half2float(hi));
}

__device__ __forceinline__ void mma16816(float c[4], const unsigned a[4], unsigned b0, unsigned b1){
    asm volatile(
      "mma.sync.aligned.m16n8k16.row.col.f32.f16.f16.f32 "
      "{%0,%1,%2,%3},{%4,%5,%6,%7},{%8,%9},{%0,%1,%2,%3};\n"
      : "+f"(c[0]), "+f"(c[1]), "+f"(c[2]), "+f"(c[3])
      : "r"(a[0]), "r"(a[1]), "r"(a[2]), "r"(a[3]), "r"(b0), "r"(b1));
}

__device__ __forceinline__ void ldsm4(unsigned addr, unsigned r[4]){
    asm volatile("ldmatrix.sync.aligned.m8n8.x4.shared.b16 {%0,%1,%2,%3}, [%4];\n"
      : "=r"(r[0]), "=r"(r[1]), "=r"(r[2]), "=r"(r[3]) : "r"(addr));
}

__device__ __forceinline__ void ldsm4t(unsigned addr, unsigned r[4]){
    asm volatile("ldmatrix.sync.aligned.m8n8.x4.trans.shared.b16 {%0,%1,%2,%3}, [%4];\n"
      : "=r"(r[0]), "=r"(r[1]), "=r"(r[2]), "=r"(r[3]) : "r"(addr));
}

__device__ __forceinline__ void cpa16(unsigned dst, const void* src){
    asm volatile("cp.async.cg.shared.global [%0], [%1], 16;\n" :: "r"(dst), "l"(src) : "memory");
}
__device__ __forceinline__ void cpa4(unsigned dst, const void* src){
    asm volatile("cp.async.ca.shared.global [%0], [%1], 4;\n" :: "r"(dst), "l"(src) : "memory");
}
#define CP_COMMIT()  asm volatile("cp.async.commit_group;\n" ::: "memory")
#define CP_WAIT0()   asm volatile("cp.async.wait_group 0;\n" ::: "memory")
#define CP_WAIT1()   asm volatile("cp.async.wait_group 1;\n" ::: "memory")

__global__ void prep_weights(const float* __restrict__ Wq, const float* __restrict__ Wk,
                             const float* __restrict__ Wv, const float* __restrict__ Wp){
    int i0 = blockIdx.x*blockDim.x + threadIdx.x, st = gridDim.x*blockDim.x;
    for (int i=i0; i<D*CIN; i+=st){ int n=i/CIN, k=i%CIN; gWq_h[i] = __float2half_rn(Wq[k*D+n]); }
    for (int i=i0; i<2*D*CIN; i+=st){ int n=i/CIN, k=i%CIN;
        float v = (n<D) ? Wk[k*D+n] : Wv[k*D+n-D]; gWkv_h[i] = __float2half_rn(v); }
    for (int i=i0; i<D*D; i+=st){ int n=i/D, k=i%D; gWp_h[i] = __float2half_rn(Wp[k*D+n]); }
}

// ---------------- 64 x (32*NWT) tile GEMM; A read exactly once (full-N CTA) ----------------
// warps 2x4: wm = warp>>2 (M 2x32), wn = warp&3 (N 4x(NWT*8))
// smem halves: Ahi 2x2560 @0 | B 2xBSZ @5120 | Alo 2x2560 @5120+2*BSZ (NPROD==2)
#define ASTR 40
#define ABUF 2560
template<int EPI, int NWT, int NPROD>
__global__ __launch_bounds__(256,1)
void gemmM64(int KT, const float* __restrict__ A,
             const float* __restrict__ bias0, const float* __restrict__ bias1,
             float* __restrict__ outF)
{
    constexpr int NTOT = NWT*32;            // total N (4 warps * NWT * 8)
    constexpr int BSZ  = NTOT*ASTR;         // halves per B buffer
    constexpr int LOB  = 5120 + 2*BSZ;      // A-lo base (halves)

    extern __shared__ __half smh[];
    const int tid = threadIdx.x, lane = tid&31, warp = tid>>5;
    const int wm = warp>>2, wn = warp&3;
    const int m0 = blockIdx.x*64;
    const __half* Bg = (EPI==0)?gWq_h:(EPI==1)?gWkv_h:gWp_h;
    const float*  Ap = (EPI==2)?gO:A;

    // A staging: 64 rows x 32 cols fp32 = 512 float4; 2 per thread
    const int arA[2] = { (tid)>>3, (tid+256)>>3 };
    const int acA    = (tid&7)<<2;
    // B staging: NTOT rows x 32 cols fp16 = NTOT*4 chunks of 16B
    const int brB0 = tid>>2;
    const int bcB  = (tid&3)<<3;

    const unsigned smb = (unsigned)__cvta_generic_to_shared(smh);
    const int aoff = (wm*32 + (lane&15))*ASTR + ((lane&16)?8:0);
    const int boff = (wn*NWT*8 + (lane&7) + ((lane&16)?8:0))*ASTR + ((lane&8)?8:0);

    float acc[2][NWT][4] = {};
    float4 pa[2];

    const int NS = KT >> 5;

    // prologue: B slab 0 (cp.async), A slab 0 (LDG+fsplit+STS)
    #pragma unroll
    for (int j=0;j<NWT/2;j++)
        cpa16(smb + (5120u + (unsigned)((brB0 + j*64)*ASTR + bcB))*2u,
              Bg + (size_t)(brB0 + j*64)*KT + bcB);
    CP_COMMIT();
    #pragma unroll
    for (int i=0;i<2;i++) pa[i] = *(const float4*)(Ap + (size_t)(m0+arA[i])*KT + acA);
    #pragma unroll
    for (int i=0;i<2;i++){
        int o = arA[i]*ASTR + acA;
        __half h0,h1,h2,h3,l0,l1,l2,l3;
        fsplit(pa[i].x,h0,l0); fsplit(pa[i].y,h1,l1);
        fsplit(pa[i].z,h2,l2); fsplit(pa[i].w,h3,l3);
        *(__half2*)&smh[o]   = __halves2half2(h0,h1);
        *(__half2*)&smh[o+2] = __halves2half2(h2,h3);
        if (NPROD==2){
            *(__half2*)&smh[LOB+o]   = __halves2half2(l0,l1);
            *(__half2*)&smh[LOB+o+2] = __halves2half2(l2,l3);
        }
    }

    for (int s=0; s<NS; s++){
        const int buf = s&1, nb = buf^1;
        const bool more = (s+1 < NS);
        if (more){
            const int kk = (s+1)<<5;
            #pragma unroll
            for (int j=0;j<NWT/2;j++)
                cpa16(smb + (5120u + (unsigned)(nb*BSZ + (brB0 + j*64)*ASTR + bcB))*2u,
                      Bg + (size_t)(brB0 + j*64)*KT + kk + bcB);
            CP_COMMIT();
            #pragma unroll
            for (int i=0;i<2;i++) pa[i] = *(const float4*)(Ap + (size_t)(m0+arA[i])*KT + kk + acA);
            CP_WAIT1();
        } else {
            CP_WAIT0();
        }
        __syncthreads();

        const unsigned aH = smb + (unsigned)(buf*ABUF + aoff)*2u;
        const unsigned aL = smb + (unsigned)(LOB + buf*ABUF + aoff)*2u;
        const unsigned bB = smb + (unsigned)(5120 + buf*BSZ + boff)*2u;
        #pragma unroll
        for (int ks=0; ks<2; ks++){
            unsigned ah[2][4], al[2][4];
            #pragma unroll
            for (int mt=0;mt<2;mt++){
                ldsm4(aH + (unsigned)(mt*16*ASTR + ks*16)*2u, ah[mt]);
                if (NPROD==2) ldsm4(aL + (unsigned)(mt*16*ASTR + ks*16)*2u, al[mt]);
            }
            #pragma unroll
            for (int nt2=0; nt2<NWT/2; nt2++){
                unsigned bb[4];
                ldsm4(bB + (unsigned)(nt2*16*ASTR + ks*16)*2u, bb);
                #pragma unroll
                for (int mt=0;mt<2;mt++){
                    mma16816(acc[mt][2*nt2],   ah[mt], bb[0], bb[1]);
                    mma16816(acc[mt][2*nt2+1], ah[mt], bb[2], bb[3]);
                    if (NPROD==2){
                        mma16816(acc[mt][2*nt2],   al[mt], bb[0], bb[1]);
                        mma16816(acc[mt][2*nt2+1], al[mt], bb[2], bb[3]);
                    }
                }
            }
        }
        if (more){
            #pragma unroll
            for (int i=0;i<2;i++){
                int o = nb*ABUF + arA[i]*ASTR + acA;
                __half h0,h1,h2,h3,l0,l1,l2,l3;
                fsplit(pa[i].x,h0,l0); fsplit(pa[i].y,h1,l1);
                fsplit(pa[i].z,h2,l2); fsplit(pa[i].w,h3,l3);
                *(__half2*)&smh[o]   = __halves2half2(h0,h1);
                *(__half2*)&smh[o+2] = __halves2half2(h2,h3);
                if (NPROD==2){
                    *(__half2*)&smh[LOB+o]   = __halves2half2(l0,l1);
                    *(__half2*)&smh[LOB+o+2] = __halves2half2(l2,l3);
                }
            }
        }
        __syncthreads();
    }

    #pragma unroll
    for (int mt=0;mt<2;mt++){
        #pragma unroll
        for (int nt=0;nt<NWT;nt++){
            int r = m0 + wm*32 + mt*16 + (lane>>2);
            int c = wn*NWT*8 + nt*8 + (lane&3)*2;
            float v00=acc[mt][nt][0], v01=acc[mt][nt][1];
            float v10=acc[mt][nt][2], v11=acc[mt][nt][3];
            if (EPI == 0){
                float b0=bias0[c], b1=bias0[c+1];
                *(__half2*)&gQh[(size_t)r*D+c]     = __floats2half2_rn(v00+b0, v01+b1);
                *(__half2*)&gQh[(size_t)(r+8)*D+c] = __floats2half2_rn(v10+b0, v11+b1);
            } else if (EPI == 1){
                bool isV = (c >= D);
                __half* dst = isV ? gV : gK;
                const float* bb = isV ? bias1 : bias0;
                int cc = c & (D-1);
                float b0=bb[cc], b1=bb[cc+1];
                *(__half2*)&dst[(size_t)r*D+cc]     = __floats2half2_rn(v00+b0, v01+b1);
                *(__half2*)&dst[(size_t)(r+8)*D+cc] = __floats2half2_rn(v10+b0, v11+b1);
            } else {
                float b0=bias0[c], b1=bias0[c+1];
                outF[(size_t)r*D+c]       = v00+b0;
                outF[(size_t)r*D+c+1]     = v01+b1;
                outF[(size_t)(r+8)*D+c]   = v10+b0;
                outF[(size_t)(r+8)*D+c+1] = v11+b1;
            }
        }
    }
}
#define SM_Q  51200   // 5120 + 2*256*40 halves -> bytes: (5120+20480)*2
#define SM_KV 92160   // (5120+40960)*2
#define SM_O  61440   // (5120+20480+5120)*2

// ---------------- attention (unchanged) ----------------
#define OFF_PL 33792u
#define OFF_KV 55296u
#define OFF_S  139776u
#define OFF_M  180736u
#define SMEM_BYTES 190464
__global__ __launch_bounds__(256)
void attn_kernel(const float* __restrict__ mask)
{
    extern __shared__ char sm[];
    __half* sQ  = (__half*)sm;
    __half* sPl = (__half*)(sm + OFF_PL);
    __half* sKV = (__half*)(sm + OFF_KV);
    float*  sS  = (float*)(sm + OFF_S);
    float*  sM  = (float*)(sm + OFF_M);
    __half* sPh = sQ;

    const int tid = threadIdx.x, lane = tid&31, warp = tid>>5;
    const int t = blockIdx.x;
    const size_t qb = (size_t)t*WA*D, kvb = (size_t)t*3*WA*D;
    const unsigned smb = (unsigned)__cvta_generic_to_shared(sm);

    for (int i=tid; i<49*32; i+=256){ int r=i>>5, g=(i&31)<<3;
        cpa16(smb + (unsigned)(r*264+g)*2u, gQh + qb + (size_t)r*D + g); }
    for (int i=tid; i<147*32; i+=256){ int r=i>>5, g=(i&31)<<3;
        cpa16(smb + OFF_KV + (unsigned)(r*264+g)*2u, gK + kvb + (size_t)r*D + g); }
    CP_COMMIT();
    for (int i=tid; i<WA*WA; i+=256)
        cpa4(smb + OFF_M + (unsigned)i*4u, mask + (size_t)(t&63)*WA*WA + i);
    CP_COMMIT();
    for (int i=tid; i<13*33; i+=256){ int r=147 + i/33, c=(i%33)*8;
        *(uint4*)&sKV[r*264+c] = make_uint4(0,0,0,0); }
    CP_WAIT1();
    __syncthreads();

    {
        const int wmS = warp>>1, wnS = warp&1;
        const unsigned aQ = smb + (unsigned)((wmS*16 + (lane&15))*264 + ((lane&16)?8:0))*2u;
        const unsigned bK = smb + OFF_KV
            + (unsigned)((wnS*80 + (lane&7) + ((lane&16)?8:0))*264 + ((lane&8)?8:0))*2u;
        float acc[10][4] = {};
        #pragma unroll
        for (int ks=0; ks<16; ks++){
            unsigned ah[4];
            ldsm4(aQ + ks*32u, ah);
            #pragma unroll
            for (int nt2=0; nt2<5; nt2++){
                unsigned bb[4];
                ldsm4(bK + (unsigned)(nt2*16*264)*2u + ks*32u, bb);
                mma16816(acc[2*nt2],   ah, bb[0], bb[1]);
                mma16816(acc[2*nt2+1], ah, bb[2], bb[3]);
            }
        }
        #pragma unroll
        for (int j=0;j<10;j++){
            int r = wmS*16 + (lane>>2), c = (wnS*10+j)*8 + (lane&3)*2;
            sS[r*160+c]=acc[j][0]; sS[r*160+c+1]=acc[j][1];
            sS[(r+8)*160+c]=acc[j][2]; sS[(r+8)*160+c+1]=acc[j][3];
        }
    }
    CP_WAIT0();
    __syncthreads();

    for (int i=tid; i<147*32; i+=256){ int r=i>>5, g=(i&31)<<3;
        cpa16(smb + OFF_KV + (unsigned)(r*264+g)*2u, gV + kvb + (size_t)r*D + g); }
    CP_COMMIT();

    for (int r=warp; r<49; r+=8){
        float vals[5]; float mx = -1e30f;
        #pragma unroll
        for (int i=0;i<5;i++){ int c = lane + 32*i; float v = -1e30f;
            if (c < 147){ int cm = (c>=98)?c-98:(c>=49)?c-49:c;
                v = sS[r*160+c]*SCALE_F + sM[r*49+cm]; }
            vals[i]=v; mx=fmaxf(mx,v); }
        #pragma unroll
        for (int o=16;o;o>>=1) mx = fmaxf(mx, __shfl_xor_sync(0xffffffffu, mx, o));
        float s = 0.f;
        #pragma unroll
        for (int i=0;i<5;i++){ int c = lane + 32*i;
            float e = (c<147) ? __expf(vals[i]-mx) : 0.f; vals[i]=e; s+=e; }
        #pragma unroll
        for (int o=16;o;o>>=1) s += __shfl_xor_sync(0xffffffffu, s, o);
        float inv = 1.f/s;
        #pragma unroll
        for (int i=0;i<5;i++){ int c = lane + 32*i; float p = vals[i]*inv;
            __half h,l; fsplit(p,h,l); sPh[r*168+c]=h; sPl[r*168+c]=l; }
    }
    for (int i=tid; i<15*21; i+=256){ int r=49 + i/21, c=(i%21)*8;
        *(uint4*)&sPh[r*168+c] = make_uint4(0,0,0,0);
        *(uint4*)&sPl[r*168+c] = make_uint4(0,0,0,0); }
    CP_WAIT0();
    __syncthreads();

    {
        const int wmP = warp&1, wnP = warp>>1;
        const unsigned aPh = smb + (unsigned)((wmP*32 + (lane&15))*168 + ((lane&16)?8:0))*2u;
        const unsigned aPl = aPh + OFF_PL;
        const unsigned bV  = smb + OFF_KV
            + (unsigned)((lane&15)*264 + wnP*64 + ((lane&16)?8:0))*2u;
        float acc[2][8][4] = {};
        #pragma unroll
        for (int ks=0; ks<10; ks++){
            unsigned ph[2][4], pl[2][4];
            #pragma unroll
            for (int mt=0;mt<2;mt++){
                ldsm4(aPh + (unsigned)(mt*16*168 + ks*16)*2u, ph[mt]);
                ldsm4(aPl + (unsigned)(mt*16*168 + ks*16)*2u, pl[mt]);
            }
            #pragma unroll
            for (int nt2=0; nt2<4; nt2++){
                unsigned vb[4];
                ldsm4t(bV + (unsigned)(ks*16*264 + nt2*16)*2u, vb);
                #pragma unroll
                for (int mt=0;mt<2;mt++){
                    mma16816(acc[mt][2*nt2],   ph[mt], vb[0], vb[1]);
                    mma16816(acc[mt][2*nt2],   pl[mt], vb[0], vb[1]);
                    mma16816(acc[mt][2*nt2+1], ph[mt], vb[2], vb[3]);
                    mma16816(acc[mt][2*nt2+1], pl[mt], vb[2], vb[3]);
                }
            }
        }
        float* Ow = gO + (size_t)t*WA*D;
        #pragma unroll
        for (int mt=0;mt<2;mt++){
            #pragma unroll
            for (int nt=0;nt<8;nt++){
                int q  = wmP*32 + mt*16 + (lane>>2);
                int d0 = wnP*64 + nt*8 + (lane&3)*2;
                if (q < 49){
                    Ow[d0*49+q]     = acc[mt][nt][0];
                    Ow[(d0+1)*49+q] = acc[mt][nt][1];
                }
                if (q+8 < 49){
                    Ow[d0*49+q+8]     = acc[mt][nt][2];
                    Ow[(d0+1)*49+q+8] = acc[mt][nt][3];
                }
            }
        }
    }
}

extern "C" void kernel_launch(void* const* d_in, const int* in_sizes, int n_in,
                              void* d_out, int out_size)
{
    const float* x    = (const float*)d_in[0];
    const float* mask = (const float*)d_in[1];
    const float* Wq = (const float*)d_in[2]; const float* bq = (const float*)d_in[3];
    const float* Wk = (const float*)d_in[4]; const float* bk = (const float*)d_in[5];
    const float* Wv = (const float*)d_in[6]; const float* bv = (const float*)d_in[7];
    const float* Wp = (const float*)d_in[8]; const float* bp = (const float*)d_in[9];
    float* out = (float*)d_out;

    cudaFuncSetAttribute(attn_kernel, cudaFuncAttributeMaxDynamicSharedMemorySize, SMEM_BYTES);
    cudaFuncSetAttribute((gemmM64<0,8,1>),  cudaFuncAttributeMaxDynamicSharedMemorySize, SM_Q);
    cudaFuncSetAttribute((gemmM64<1,16,1>), cudaFuncAttributeMaxDynamicSharedMemorySize, SM_KV);
    cudaFuncSetAttribute((gemmM64<2,8,2>),  cudaFuncAttributeMaxDynamicSharedMemorySize, SM_O);

    prep_weights<<<256,256>>>(Wq, Wk, Wv, Wp);
    gemmM64<0,8,1><<<NQ/64, 256, SM_Q>>>(CIN, x + (size_t)3*TW*WA*CIN, bq, nullptr, nullptr);
    gemmM64<1,16,1><<<NKV/64, 256, SM_KV>>>(CIN, x, bk, bv, nullptr);
    attn_kernel<<<TW, 256, SMEM_BYTES>>>(mask);
    gemmM64<2,8,2><<<NQ/64, 256, SM_O>>>(D, nullptr, bp, nullptr, out);
}

// round 15
// speedup vs baseline: 1.2319x; 1.2319x over previous
#include <cuda_runtime.h>
#include <cuda_fp16.h>
#include <cstdint>

#define TW 2048
#define WA 49
#define NQ (TW*WA)
#define NKV (3*TW*WA)
#define CIN 512
#define D 256
#define SCALE_F 0.17677669529663687f

__device__ __half gWq_h[D*CIN];
__device__ __half gWkv_h[2*D*CIN];
__device__ __half gWp_h[D*D];
__device__ __half gQh[(size_t)NQ*D];
__device__ __half gK[(size_t)NKV*D], gV[(size_t)NKV*D];
__device__ float  gO[(size_t)NQ*D];

__device__ __forceinline__ void fsplit(float v, __half& hi, __half& lo){
    hi = __float2half_rn(v);
    lo = __float2half_rn(v - __half2float(hi));
}

__device__ __forceinline__ void mma16816(float c[4], const unsigned a[4], unsigned b0, unsigned b1){
    asm volatile(
      "mma.sync.aligned.m16n8k16.row.col.f32.f16.f16.f32 "
      "{%0,%1,%2,%3},{%4,%5,%6,%7},{%8,%9},{%0,%1,%2,%3};\n"
      : "+f"(c[0]), "+f"(c[1]), "+f"(c[2]), "+f"(c[3])
      : "r"(a[0]), "r"(a[1]), "r"(a[2]), "r"(a[3]), "r"(b0), "r"(b1));
}

__device__ __forceinline__ void ldsm4(unsigned addr, unsigned r[4]){
    asm volatile("ldmatrix.sync.aligned.m8n8.x4.shared.b16 {%0,%1,%2,%3}, [%4];\n"
      : "=r"(r[0]), "=r"(r[1]), "=r"(r[2]), "=r"(r[3]) : "r"(addr));
}
__device__ __forceinline__ void ldsm4t(unsigned addr, unsigned r[4]){
    asm volatile("ldmatrix.sync.aligned.m8n8.x4.trans.shared.b16 {%0,%1,%2,%3}, [%4];\n"
      : "=r"(r[0]), "=r"(r[1]), "=r"(r[2]), "=r"(r[3]) : "r"(addr));
}
__device__ __forceinline__ void cpa16(unsigned dst, const void* src){
    asm volatile("cp.async.cg.shared.global [%0], [%1], 16;\n" :: "r"(dst), "l"(src) : "memory");
}
__device__ __forceinline__ void cpa4(unsigned dst, const void* src){
    asm volatile("cp.async.ca.shared.global [%0], [%1], 4;\n" :: "r"(dst), "l"(src) : "memory");
}
#define CP_COMMIT()  asm volatile("cp.async.commit_group;\n" ::: "memory")
#define CP_WAIT0()   asm volatile("cp.async.wait_group 0;\n" ::: "memory")
#define CP_WAIT1()   asm volatile("cp.async.wait_group 1;\n" ::: "memory")

__global__ void prep_weights(const float* __restrict__ Wq, const float* __restrict__ Wk,
                             const float* __restrict__ Wv, const float* __restrict__ Wp){
    int i0 = blockIdx.x*blockDim.x + threadIdx.x, st = gridDim.x*blockDim.x;
    for (int i=i0; i<D*CIN; i+=st){ int n=i/CIN, k=i%CIN; gWq_h[i] = __float2half_rn(Wq[k*D+n]); }
    for (int i=i0; i<2*D*CIN; i+=st){ int n=i/CIN, k=i%CIN;
        float v = (n<D) ? Wk[k*D+n] : Wv[k*D+n-D]; gWkv_h[i] = __float2half_rn(v); }
    for (int i=i0; i<D*D; i+=st){ int n=i/D, k=i%D; gWp_h[i] = __float2half_rn(Wp[k*D+n]); }
}

// ------- 128x128 tile GEMM, NPROD products, cp.async B, dbl-buffered, 2 CTAs/SM -------
// warps 2x4: wm = warp>>2 (2 x 64 rows), wn = warp&3 (4 x 32 cols)
// smem halves: sAh 2x5120 @0 | sB 2x5120 @10240 | sAl 2x5120 @20480 (NPROD==2)
#define ASTR 40
#define ABUF 5120
template<int EPI, int NPROD>
__global__ __launch_bounds__(256,2)
void gemm128b(int KT, const float* __restrict__ A,
              const float* __restrict__ bias0, const float* __restrict__ bias1,
              float* __restrict__ outF)
{
    extern __shared__ __half smh[];
    const int tid = threadIdx.x, lane = tid&31, warp = tid>>5;
    const int wm = warp>>2, wn = warp&3;
    const int m0 = blockIdx.y*128, n0 = blockIdx.x*128;
    const __half* Bg = (EPI==0)?gWq_h:(EPI==1)?gWkv_h:gWp_h;
    const float*  Ap = (EPI==2)?gO:A;

    // A staging: 128r x 32c fp32 = 1024 float4, 4/thread
    const int arA[4] = { (tid)>>3, (tid+256)>>3, (tid+512)>>3, (tid+768)>>3 };
    const int acA    = (tid&7)<<2;
    // B staging: 128r x 32c fp16 = 512 x 16B, 2/thread
    const int brB[2] = { tid>>2, (tid>>2)+64 };
    const int bcB    = (tid&3)<<3;

    const unsigned smb = (unsigned)__cvta_generic_to_shared(smh);
    const int aoff = (wm*64 + (lane&15))*ASTR + ((lane&16)?8:0);
    const int boff = (wn*32 + (lane&7) + ((lane&16)?8:0))*ASTR + ((lane&8)?8:0);

    float acc[4][4][4] = {};
    float4 pa[4];

    const int NS = KT >> 5;

    // prologue: slab 0
    #pragma unroll
    for (int i=0;i<2;i++)
        cpa16(smb + (10240u + (unsigned)(brB[i]*ASTR + bcB))*2u,
              Bg + (size_t)(n0+brB[i])*KT + bcB);
    CP_COMMIT();
    #pragma unroll
    for (int i=0;i<4;i++) pa[i] = *(const float4*)(Ap + (size_t)(m0+arA[i])*KT + acA);
    #pragma unroll
    for (int i=0;i<4;i++){
        int o = arA[i]*ASTR + acA;
        __half h0,h1,h2,h3,l0,l1,l2,l3;
        fsplit(pa[i].x,h0,l0); fsplit(pa[i].y,h1,l1);
        fsplit(pa[i].z,h2,l2); fsplit(pa[i].w,h3,l3);
        *(__half2*)&smh[o]   = __halves2half2(h0,h1);
        *(__half2*)&smh[o+2] = __halves2half2(h2,h3);
        if (NPROD==2){
            *(__half2*)&smh[20480+o]   = __halves2half2(l0,l1);
            *(__half2*)&smh[20480+o+2] = __halves2half2(l2,l3);
        }
    }

    for (int s=0; s<NS; s++){
        const int buf = s&1, nb = buf^1;
        const bool more = (s+1 < NS);
        if (more){
            const int kk = (s+1)<<5;
            #pragma unroll
            for (int i=0;i<2;i++)
                cpa16(smb + (10240u + (unsigned)(nb*ABUF + brB[i]*ASTR + bcB))*2u,
                      Bg + (size_t)(n0+brB[i])*KT + kk + bcB);
            CP_COMMIT();
            #pragma unroll
            for (int i=0;i<4;i++) pa[i] = *(const float4*)(Ap + (size_t)(m0+arA[i])*KT + kk + acA);
            CP_WAIT1();
        } else {
            CP_WAIT0();
        }
        __syncthreads();

        const unsigned aH = smb + (unsigned)(buf*ABUF + aoff)*2u;
        const unsigned aL = smb + (unsigned)(20480 + buf*ABUF + aoff)*2u;
        const unsigned bB = smb + (unsigned)(10240 + buf*ABUF + boff)*2u;
        #pragma unroll
        for (int ks=0; ks<2; ks++){
            unsigned ah[4][4], al[4][4];
            #pragma unroll
            for (int mt=0;mt<4;mt++){
                ldsm4(aH + (unsigned)(mt*16*ASTR + ks*16)*2u, ah[mt]);
                if (NPROD==2) ldsm4(aL + (unsigned)(mt*16*ASTR + ks*16)*2u, al[mt]);
            }
            #pragma unroll
            for (int nt2=0; nt2<2; nt2++){
                unsigned bb[4];
                ldsm4(bB + (unsigned)(nt2*16*ASTR + ks*16)*2u, bb);
                #pragma unroll
                for (int mt=0;mt<4;mt++){
                    mma16816(acc[mt][2*nt2],   ah[mt], bb[0], bb[1]);
                    mma16816(acc[mt][2*nt2+1], ah[mt], bb[2], bb[3]);
                    if (NPROD==2){
                        mma16816(acc[mt][2*nt2],   al[mt], bb[0], bb[1]);
                        mma16816(acc[mt][2*nt2+1], al[mt], bb[2], bb[3]);
                    }
                }
            }
        }
        if (more){
            #pragma unroll
            for (int i=0;i<4;i++){
                int o = nb*ABUF + arA[i]*ASTR + acA;
                __half h0,h1,h2,h3,l0,l1,l2,l3;
                fsplit(pa[i].x,h0,l0); fsplit(pa[i].y,h1,l1);
                fsplit(pa[i].z,h2,l2); fsplit(pa[i].w,h3,l3);
                *(__half2*)&smh[o]   = __halves2half2(h0,h1);
                *(__half2*)&smh[o+2] = __halves2half2(h2,h3);
                if (NPROD==2){
                    *(__half2*)&smh[20480+o]   = __halves2half2(l0,l1);
                    *(__half2*)&smh[20480+o+2] = __halves2half2(l2,l3);
                }
            }
        }
        __syncthreads();
    }

    #pragma unroll
    for (int mt=0;mt<4;mt++){
        #pragma unroll
        for (int nt=0;nt<4;nt++){
            int r = m0 + wm*64 + mt*16 + (lane>>2);
            int c = n0 + wn*32 + nt*8 + (lane&3)*2;
            float v00=acc[mt][nt][0], v01=acc[mt][nt][1];
            float v10=acc[mt][nt][2], v11=acc[mt][nt][3];
            if (EPI == 0){
                float b0=bias0[c], b1=bias0[c+1];
                *(__half2*)&gQh[(size_t)r*D+c]     = __floats2half2_rn(v00+b0, v01+b1);
                *(__half2*)&gQh[(size_t)(r+8)*D+c] = __floats2half2_rn(v10+b0, v11+b1);
            } else if (EPI == 1){
                bool isV = (c >= D);
                __half* dst = isV ? gV : gK;
                const float* bb = isV ? bias1 : bias0;
                int cc = c & (D-1);
                float b0=bb[cc], b1=bb[cc+1];
                *(__half2*)&dst[(size_t)r*D+cc]     = __floats2half2_rn(v00+b0, v01+b1);
                *(__half2*)&dst[(size_t)(r+8)*D+cc] = __floats2half2_rn(v10+b0, v11+b1);
            } else {
                float b0=bias0[c], b1=bias0[c+1];
                outF[(size_t)r*D+c]       = v00+b0;
                outF[(size_t)r*D+c+1]     = v01+b1;
                outF[(size_t)(r+8)*D+c]   = v10+b0;
                outF[(size_t)(r+8)*D+c+1] = v11+b1;
            }
        }
    }
}
#define SM_G1 40960
#define SM_G2 61440

// ---------------- attention (R12 best, unchanged) ----------------
#define OFF_PL 33792u
#define OFF_KV 55296u
#define OFF_S  139776u
#define OFF_M  180736u
#define SMEM_BYTES 190464
__global__ __launch_bounds__(256)
void attn_kernel(const float* __restrict__ mask)
{
    extern __shared__ char sm[];
    __half* sKV = (__half*)(sm + OFF_KV);
    float*  sS  = (float*)(sm + OFF_S);
    float*  sM  = (float*)(sm + OFF_M);
    __half* sPh = (__half*)sm;
    __half* sPl = (__half*)(sm + OFF_PL);

    const int tid = threadIdx.x, lane = tid&31, warp = tid>>5;
    const int t = blockIdx.x;
    const size_t qb = (size_t)t*WA*D, kvb = (size_t)t*3*WA*D;
    const unsigned smb = (unsigned)__cvta_generic_to_shared(sm);

    for (int i=tid; i<49*32; i+=256){ int r=i>>5, g=(i&31)<<3;
        cpa16(smb + (unsigned)(r*264+g)*2u, gQh + qb + (size_t)r*D + g); }
    for (int i=tid; i<147*32; i+=256){ int r=i>>5, g=(i&31)<<3;
        cpa16(smb + OFF_KV + (unsigned)(r*264+g)*2u, gK + kvb + (size_t)r*D + g); }
    CP_COMMIT();
    for (int i=tid; i<WA*WA; i+=256)
        cpa4(smb + OFF_M + (unsigned)i*4u, mask + (size_t)(t&63)*WA*WA + i);
    CP_COMMIT();
    for (int i=tid; i<13*33; i+=256){ int r=147 + i/33, c=(i%33)*8;
        *(uint4*)&sKV[r*264+c] = make_uint4(0,0,0,0); }
    CP_WAIT1();
    __syncthreads();

    {
        const int wmS = warp>>1, wnS = warp&1;
        const unsigned aQ = smb + (unsigned)((wmS*16 + (lane&15))*264 + ((lane&16)?8:0))*2u;
        const unsigned bK = smb + OFF_KV
            + (unsigned)((wnS*80 + (lane&7) + ((lane&16)?8:0))*264 + ((lane&8)?8:0))*2u;
        float acc[10][4] = {};
        #pragma unroll
        for (int ks=0; ks<16; ks++){
            unsigned ah[4];
            ldsm4(aQ + ks*32u, ah);
            #pragma unroll
            for (int nt2=0; nt2<5; nt2++){
                unsigned bb[4];
                ldsm4(bK + (unsigned)(nt2*16*264)*2u + ks*32u, bb);
                mma16816(acc[2*nt2],   ah, bb[0], bb[1]);
                mma16816(acc[2*nt2+1], ah, bb[2], bb[3]);
            }
        }
        #pragma unroll
        for (int j=0;j<10;j++){
            int r = wmS*16 + (lane>>2), c = (wnS*10+j)*8 + (lane&3)*2;
            sS[r*160+c]=acc[j][0]; sS[r*160+c+1]=acc[j][1];
            sS[(r+8)*160+c]=acc[j][2]; sS[(r+8)*160+c+1]=acc[j][3];
        }
    }
    CP_WAIT0();
    __syncthreads();

    for (int i=tid; i<147*32; i+=256){ int r=i>>5, g=(i&31)<<3;
        cpa16(smb + OFF_KV + (unsigned)(r*264+g)*2u, gV + kvb + (size_t)r*D + g); }
    CP_COMMIT();

    for (int r=warp; r<49; r+=8){
        float vals[5]; float mx = -1e30f;
        #pragma unroll
        for (int i=0;i<5;i++){ int c = lane + 32*i; float v = -1e30f;
            if (c < 147){ int cm = (c>=98)?c-98:(c>=49)?c-49:c;
                v = sS[r*160+c]*SCALE_F + sM[r*49+cm]; }
            vals[i]=v; mx=fmaxf(mx,v); }
        #pragma unroll
        for (int o=16;o;o>>=1) mx = fmaxf(mx, __shfl_xor_sync(0xffffffffu, mx, o));
        float s = 0.f;
        #pragma unroll
        for (int i=0;i<5;i++){ int c = lane + 32*i;
            float e = (c<147) ? __expf(vals[i]-mx) : 0.f; vals[i]=e; s+=e; }
        #pragma unroll
        for (int o=16;o;o>>=1) s += __shfl_xor_sync(0xffffffffu, s, o);
        float inv = 1.f/s;
        #pragma unroll
        for (int i=0;i<5;i++){ int c = lane + 32*i; float pq = vals[i]*inv;
            __half h,l; fsplit(pq,h,l); sPh[r*168+c]=h; sPl[r*168+c]=l; }
    }
    for (int i=tid; i<15*21; i+=256){ int r=49 + i/21, c=(i%21)*8;
        *(uint4*)&sPh[r*168+c] = make_uint4(0,0,0,0);
        *(uint4*)&sPl[r*168+c] = make_uint4(0,0,0,0); }
    CP_WAIT0();
    __syncthreads();

    {
        const int wmP = warp&1, wnP = warp>>1;
        const unsigned aPh = smb + (unsigned)((wmP*32 + (lane&15))*168 + ((lane&16)?8:0))*2u;
        const unsigned aPl = aPh + OFF_PL;
        const unsigned bV  = smb + OFF_KV
            + (unsigned)((lane&15)*264 + wnP*64 + ((lane&16)?8:0))*2u;
        float acc[2][8][4] = {};
        #pragma unroll
        for (int ks=0; ks<10; ks++){
            unsigned ph[2][4], pl[2][4];
            #pragma unroll
            for (int mt=0;mt<2;mt++){
                ldsm4(aPh + (unsigned)(mt*16*168 + ks*16)*2u, ph[mt]);
                ldsm4(aPl + (unsigned)(mt*16*168 + ks*16)*2u, pl[mt]);
            }
            #pragma unroll
            for (int nt2=0; nt2<4; nt2++){
                unsigned vb[4];
                ldsm4t(bV + (unsigned)(ks*16*264 + nt2*16)*2u, vb);
                #pragma unroll
                for (int mt=0;mt<2;mt++){
                    mma16816(acc[mt][2*nt2],   ph[mt], vb[0], vb[1]);
                    mma16816(acc[mt][2*nt2],   pl[mt], vb[0], vb[1]);
                    mma16816(acc[mt][2*nt2+1], ph[mt], vb[2], vb[3]);
                    mma16816(acc[mt][2*nt2+1], pl[mt], vb[2], vb[3]);
                }
            }
        }
        float* Ow = gO + (size_t)t*WA*D;
        #pragma unroll
        for (int mt=0;mt<2;mt++){
            #pragma unroll
            for (int nt=0;nt<8;nt++){
                int q  = wmP*32 + mt*16 + (lane>>2);
                int d0 = wnP*64 + nt*8 + (lane&3)*2;
                if (q < 49){
                    Ow[d0*49+q]     = acc[mt][nt][0];
                    Ow[(d0+1)*49+q] = acc[mt][nt][1];
                }
                if (q+8 < 49){
                    Ow[d0*49+q+8]     = acc[mt][nt][2];
                    Ow[(d0+1)*49+q+8] = acc[mt][nt][3];
                }
            }
        }
    }
}

extern "C" void kernel_launch(void* const* d_in, const int* in_sizes, int n_in,
                              void* d_out, int out_size)
{
    const float* x    = (const float*)d_in[0];
    const float* mask = (const float*)d_in[1];
    const float* Wq = (const float*)d_in[2]; const float* bq = (const float*)d_in[3];
    const float* Wk = (const float*)d_in[4]; const float* bk = (const float*)d_in[5];
    const float* Wv = (const float*)d_in[6]; const float* bv = (const float*)d_in[7];
    const float* Wp = (const float*)d_in[8]; const float* bp = (const float*)d_in[9];
    float* out = (float*)d_out;

    cudaFuncSetAttribute(attn_kernel, cudaFuncAttributeMaxDynamicSharedMemorySize, SMEM_BYTES);
    cudaFuncSetAttribute((gemm128b<0,1>), cudaFuncAttributeMaxDynamicSharedMemorySize, SM_G1);
    cudaFuncSetAttribute((gemm128b<1,1>), cudaFuncAttributeMaxDynamicSharedMemorySize, SM_G1);
    cudaFuncSetAttribute((gemm128b<2,2>), cudaFuncAttributeMaxDynamicSharedMemorySize, SM_G2);

    prep_weights<<<256,256>>>(Wq, Wk, Wv, Wp);
    gemm128b<0,1><<<dim3(2,784), 256, SM_G1>>>(CIN, x + (size_t)3*TW*WA*CIN, bq, nullptr, nullptr);
    gemm128b<1,1><<<dim3(4,2352), 256, SM_G1>>>(CIN, x, bk, bv, nullptr);
    attn_kernel<<<TW, 256, SMEM_BYTES>>>(mask);
    gemm128b<2,2><<<dim3(2,784), 256, SM_G2>>>(D, nullptr, bp, nullptr, out);
}

// round 16
// speedup vs baseline: 1.2687x; 1.0299x over previous
#include <cuda_runtime.h>
#include <cuda_fp16.h>
#include <cstdint>

#define TW 2048
#define WA 49
#define NQ (TW*WA)
#define NKV (3*TW*WA)
#define CIN 512
#define D 256
#define SCALE_F 0.17677669529663687f

__device__ __half gWq_h[D*CIN];
__device__ __half gWkv_h[2*D*CIN];
__device__ __half gWp_h[D*D];
__device__ __half gQh[(size_t)NQ*D];
__device__ __half gK[(size_t)NKV*D], gV[(size_t)NKV*D];
__device__ __half gOh[(size_t)NQ*D];

__device__ __forceinline__ void fsplit(float v, __half& hi, __half& lo){
    hi = __float2half_rn(v);
    lo = __float2half_rn(v - __half2float(hi));
}

__device__ __forceinline__ void mma16816(float c[4], const unsigned a[4], unsigned b0, unsigned b1){
    asm volatile(
      "mma.sync.aligned.m16n8k16.row.col.f32.f16.f16.f32 "
      "{%0,%1,%2,%3},{%4,%5,%6,%7},{%8,%9},{%0,%1,%2,%3};\n"
      : "+f"(c[0]), "+f"(c[1]), "+f"(c[2]), "+f"(c[3])
      : "r"(a[0]), "r"(a[1]), "r"(a[2]), "r"(a[3]), "r"(b0), "r"(b1));
}

__device__ __forceinline__ void ldsm4(unsigned addr, unsigned r[4]){
    asm volatile("ldmatrix.sync.aligned.m8n8.x4.shared.b16 {%0,%1,%2,%3}, [%4];\n"
      : "=r"(r[0]), "=r"(r[1]), "=r"(r[2]), "=r"(r[3]) : "r"(addr));
}
__device__ __forceinline__ void ldsm4t(unsigned addr, unsigned r[4]){
    asm volatile("ldmatrix.sync.aligned.m8n8.x4.trans.shared.b16 {%0,%1,%2,%3}, [%4];\n"
      : "=r"(r[0]), "=r"(r[1]), "=r"(r[2]), "=r"(r[3]) : "r"(addr));
}
__device__ __forceinline__ void cpa16(unsigned dst, const void* src){
    asm volatile("cp.async.cg.shared.global [%0], [%1], 16;\n" :: "r"(dst), "l"(src) : "memory");
}
__device__ __forceinline__ void cpa4(unsigned dst, const void* src){
    asm volatile("cp.async.ca.shared.global [%0], [%1], 4;\n" :: "r"(dst), "l"(src) : "memory");
}
#define CP_COMMIT()  asm volatile("cp.async.commit_group;\n" ::: "memory")
#define CP_WAIT0()   asm volatile("cp.async.wait_group 0;\n" ::: "memory")
#define CP_WAIT1()   asm volatile("cp.async.wait_group 1;\n" ::: "memory")

__global__ void prep_weights(const float* __restrict__ Wq, const float* __restrict__ Wk,
                             const float* __restrict__ Wv, const float* __restrict__ Wp){
    int i0 = blockIdx.x*blockDim.x + threadIdx.x, st = gridDim.x*blockDim.x;
    for (int i=i0; i<D*CIN; i+=st){ int n=i/CIN, k=i%CIN; gWq_h[i] = __float2half_rn(Wq[k*D+n]); }
    for (int i=i0; i<2*D*CIN; i+=st){ int n=i/CIN, k=i%CIN;
        float v = (n<D) ? Wk[k*D+n] : Wv[k*D+n-D]; gWkv_h[i] = __float2half_rn(v); }
    for (int i=i0; i<D*D; i+=st){ int n=i/D, k=i%D; gWp_h[i] = __float2half_rn(Wp[k*D+n]); }
}

// ------- 128x128 tile GEMM, dbl-buffered, 2 CTAs/SM -------
// EPI 0: Q proj (A fp32)  1: K|V proj (A fp32)  2: out proj (A fp16 = gOh, cp.async both)
// warps 2x4: wm = warp>>2 (2 x 64 rows), wn = warp&3 (4 x 32 cols)
// smem halves: sAh 2x5120 @0 | sB 2x5120 @10240
#define ASTR 40
#define ABUF 5120
template<int EPI, int AHALF>
__global__ __launch_bounds__(256,2)
void gemm128b(int KT, const float* __restrict__ A,
              const float* __restrict__ bias0, const float* __restrict__ bias1,
              float* __restrict__ outF)
{
    extern __shared__ __half smh[];
    const int tid = threadIdx.x, lane = tid&31, warp = tid>>5;
    const int wm = warp>>2, wn = warp&3;
    const int m0 = blockIdx.y*128, n0 = blockIdx.x*128;
    const __half* Bg = (EPI==0)?gWq_h:(EPI==1)?gWkv_h:gWp_h;

    // fp32-A staging: 128r x 32c fp32 = 1024 float4, 4/thread
    const int arA[4] = { (tid)>>3, (tid+256)>>3, (tid+512)>>3, (tid+768)>>3 };
    const int acA    = (tid&7)<<2;
    // fp16 staging (B always; A when AHALF): 128r x 32c fp16 = 512 x 16B, 2/thread
    const int brB[2] = { tid>>2, (tid>>2)+64 };
    const int bcB    = (tid&3)<<3;

    const unsigned smb = (unsigned)__cvta_generic_to_shared(smh);
    const int aoff = (wm*64 + (lane&15))*ASTR + ((lane&16)?8:0);
    const int boff = (wn*32 + (lane&7) + ((lane&16)?8:0))*ASTR + ((lane&8)?8:0);

    float acc[4][4][4] = {};
    float4 pa[4];

    const int NS = KT >> 5;

    // prologue: slab 0
    #pragma unroll
    for (int i=0;i<2;i++)
        cpa16(smb + (10240u + (unsigned)(brB[i]*ASTR + bcB))*2u,
              Bg + (size_t)(n0+brB[i])*KT + bcB);
    if (AHALF){
        #pragma unroll
        for (int i=0;i<2;i++)
            cpa16(smb + (unsigned)(brB[i]*ASTR + bcB)*2u,
                  gOh + (size_t)(m0+brB[i])*KT + bcB);
        CP_COMMIT();
    } else {
        CP_COMMIT();
        #pragma unroll
        for (int i=0;i<4;i++) pa[i] = *(const float4*)(A + (size_t)(m0+arA[i])*KT + acA);
        #pragma unroll
        for (int i=0;i<4;i++){
            int o = arA[i]*ASTR + acA;
            __half h0,h1,h2,h3,l0,l1,l2,l3;
            fsplit(pa[i].x,h0,l0); fsplit(pa[i].y,h1,l1);
            fsplit(pa[i].z,h2,l2); fsplit(pa[i].w,h3,l3);
            *(__half2*)&smh[o]   = __halves2half2(h0,h1);
            *(__half2*)&smh[o+2] = __halves2half2(h2,h3);
        }
    }

    for (int s=0; s<NS; s++){
        const int buf = s&1, nb = buf^1;
        const bool more = (s+1 < NS);
        if (more){
            const int kk = (s+1)<<5;
            #pragma unroll
            for (int i=0;i<2;i++)
                cpa16(smb + (10240u + (unsigned)(nb*ABUF + brB[i]*ASTR + bcB))*2u,
                      Bg + (size_t)(n0+brB[i])*KT + kk + bcB);
            if (AHALF){
                #pragma unroll
                for (int i=0;i<2;i++)
                    cpa16(smb + (unsigned)(nb*ABUF + brB[i]*ASTR + bcB)*2u,
                          gOh + (size_t)(m0+brB[i])*KT + kk + bcB);
            }
            CP_COMMIT();
            if (!AHALF){
                #pragma unroll
                for (int i=0;i<4;i++) pa[i] = *(const float4*)(A + (size_t)(m0+arA[i])*KT + kk + acA);
            }
            CP_WAIT1();
        } else {
            CP_WAIT0();
        }
        __syncthreads();

        const unsigned aH = smb + (unsigned)(buf*ABUF + aoff)*2u;
        const unsigned bB = smb + (unsigned)(10240 + buf*ABUF + boff)*2u;
        #pragma unroll
        for (int ks=0; ks<2; ks++){
            unsigned ah[4][4];
            #pragma unroll
            for (int mt=0;mt<4;mt++)
                ldsm4(aH + (unsigned)(mt*16*ASTR + ks*16)*2u, ah[mt]);
            #pragma unroll
            for (int nt2=0; nt2<2; nt2++){
                unsigned bb[4];
                ldsm4(bB + (unsigned)(nt2*16*ASTR + ks*16)*2u, bb);
                #pragma unroll
                for (int mt=0;mt<4;mt++){
                    mma16816(acc[mt][2*nt2],   ah[mt], bb[0], bb[1]);
                    mma16816(acc[mt][2*nt2+1], ah[mt], bb[2], bb[3]);
                }
            }
        }
        if (more && !AHALF){
            #pragma unroll
            for (int i=0;i<4;i++){
                int o = nb*ABUF + arA[i]*ASTR + acA;
                __half h0,h1,h2,h3,l0,l1,l2,l3;
                fsplit(pa[i].x,h0,l0); fsplit(pa[i].y,h1,l1);
                fsplit(pa[i].z,h2,l2); fsplit(pa[i].w,h3,l3);
                *(__half2*)&smh[o]   = __halves2half2(h0,h1);
                *(__half2*)&smh[o+2] = __halves2half2(h2,h3);
            }
        }
        __syncthreads();
    }

    #pragma unroll
    for (int mt=0;mt<4;mt++){
        #pragma unroll
        for (int nt=0;nt<4;nt++){
            int r = m0 + wm*64 + mt*16 + (lane>>2);
            int c = n0 + wn*32 + nt*8 + (lane&3)*2;
            float v00=acc[mt][nt][0], v01=acc[mt][nt][1];
            float v10=acc[mt][nt][2], v11=acc[mt][nt][3];
            if (EPI == 0){
                float b0=bias0[c], b1=bias0[c+1];
                *(__half2*)&gQh[(size_t)r*D+c]     = __floats2half2_rn(v00+b0, v01+b1);
                *(__half2*)&gQh[(size_t)(r+8)*D+c] = __floats2half2_rn(v10+b0, v11+b1);
            } else if (EPI == 1){
                bool isV = (c >= D);
                __half* dst = isV ? gV : gK;
                const float* bb = isV ? bias1 : bias0;
                int cc = c & (D-1);
                float b0=bb[cc], b1=bb[cc+1];
                *(__half2*)&dst[(size_t)r*D+cc]     = __floats2half2_rn(v00+b0, v01+b1);
                *(__half2*)&dst[(size_t)(r+8)*D+cc] = __floats2half2_rn(v10+b0, v11+b1);
            } else {
                float b0=bias0[c], b1=bias0[c+1];
                outF[(size_t)r*D+c]       = v00+b0;
                outF[(size_t)r*D+c+1]     = v01+b1;
                outF[(size_t)(r+8)*D+c]   = v10+b0;
                outF[(size_t)(r+8)*D+c+1] = v11+b1;
            }
        }
    }
}
#define SM_G1 40960

// ---------------- attention (R12 mainloop; fp16 O store) ----------------
#define OFF_PL 33792u
#define OFF_KV 55296u
#define OFF_S  139776u
#define OFF_M  180736u
#define SMEM_BYTES 190464
__global__ __launch_bounds__(256)
void attn_kernel(const float* __restrict__ mask)
{
    extern __shared__ char sm[];
    __half* sKV = (__half*)(sm + OFF_KV);
    float*  sS  = (float*)(sm + OFF_S);
    float*  sM  = (float*)(sm + OFF_M);
    __half* sPh = (__half*)sm;
    __half* sPl = (__half*)(sm + OFF_PL);

    const int tid = threadIdx.x, lane = tid&31, warp = tid>>5;
    const int t = blockIdx.x;
    const size_t qb = (size_t)t*WA*D, kvb = (size_t)t*3*WA*D;
    const unsigned smb = (unsigned)__cvta_generic_to_shared(sm);

    for (int i=tid; i<49*32; i+=256){ int r=i>>5, g=(i&31)<<3;
        cpa16(smb + (unsigned)(r*264+g)*2u, gQh + qb + (size_t)r*D + g); }
    for (int i=tid; i<147*32; i+=256){ int r=i>>5, g=(i&31)<<3;
        cpa16(smb + OFF_KV + (unsigned)(r*264+g)*2u, gK + kvb + (size_t)r*D + g); }
    CP_COMMIT();
    for (int i=tid; i<WA*WA; i+=256)
        cpa4(smb + OFF_M + (unsigned)i*4u, mask + (size_t)(t&63)*WA*WA + i);
    CP_COMMIT();
    for (int i=tid; i<13*33; i+=256){ int r=147 + i/33, c=(i%33)*8;
        *(uint4*)&sKV[r*264+c] = make_uint4(0,0,0,0); }
    CP_WAIT1();
    __syncthreads();

    {
        const int wmS = warp>>1, wnS = warp&1;
        const unsigned aQ = smb + (unsigned)((wmS*16 + (lane&15))*264 + ((lane&16)?8:0))*2u;
        const unsigned bK = smb + OFF_KV
            + (unsigned)((wnS*80 + (lane&7) + ((lane&16)?8:0))*264 + ((lane&8)?8:0))*2u;
        float acc[10][4] = {};
        #pragma unroll
        for (int ks=0; ks<16; ks++){
            unsigned ah[4];
            ldsm4(aQ + ks*32u, ah);
            #pragma unroll
            for (int nt2=0; nt2<5; nt2++){
                unsigned bb[4];
                ldsm4(bK + (unsigned)(nt2*16*264)*2u + ks*32u, bb);
                mma16816(acc[2*nt2],   ah, bb[0], bb[1]);
                mma16816(acc[2*nt2+1], ah, bb[2], bb[3]);
            }
        }
        #pragma unroll
        for (int j=0;j<10;j++){
            int r = wmS*16 + (lane>>2), c = (wnS*10+j)*8 + (lane&3)*2;
            sS[r*160+c]=acc[j][0]; sS[r*160+c+1]=acc[j][1];
            sS[(r+8)*160+c]=acc[j][2]; sS[(r+8)*160+c+1]=acc[j][3];
        }
    }
    CP_WAIT0();
    __syncthreads();

    for (int i=tid; i<147*32; i+=256){ int r=i>>5, g=(i&31)<<3;
        cpa16(smb + OFF_KV + (unsigned)(r*264+g)*2u, gV + kvb + (size_t)r*D + g); }
    CP_COMMIT();

    for (int r=warp; r<49; r+=8){
        float vals[5]; float mx = -1e30f;
        #pragma unroll
        for (int i=0;i<5;i++){ int c = lane + 32*i; float v = -1e30f;
            if (c < 147){ int cm = (c>=98)?c-98:(c>=49)?c-49:c;
                v = sS[r*160+c]*SCALE_F + sM[r*49+cm]; }
            vals[i]=v; mx=fmaxf(mx,v); }
        #pragma unroll
        for (int o=16;o;o>>=1) mx = fmaxf(mx, __shfl_xor_sync(0xffffffffu, mx, o));
        float s = 0.f;
        #pragma unroll
        for (int i=0;i<5;i++){ int c = lane + 32*i;
            float e = (c<147) ? __expf(vals[i]-mx) : 0.f; vals[i]=e; s+=e; }
        #pragma unroll
        for (int o=16;o;o>>=1) s += __shfl_xor_sync(0xffffffffu, s, o);
        float inv = 1.f/s;
        #pragma unroll
        for (int i=0;i<5;i++){ int c = lane + 32*i; float pq = vals[i]*inv;
            __half h,l; fsplit(pq,h,l); sPh[r*168+c]=h; sPl[r*168+c]=l; }
    }
    for (int i=tid; i<15*21; i+=256){ int r=49 + i/21, c=(i%21)*8;
        *(uint4*)&sPh[r*168+c] = make_uint4(0,0,0,0);
        *(uint4*)&sPl[r*168+c] = make_uint4(0,0,0,0); }
    CP_WAIT0();
    __syncthreads();

    {
        const int wmP = warp&1, wnP = warp>>1;
        const unsigned aPh = smb + (unsigned)((wmP*32 + (lane&15))*168 + ((lane&16)?8:0))*2u;
        const unsigned aPl = aPh + OFF_PL;
        const unsigned bV  = smb + OFF_KV
            + (unsigned)((lane&15)*264 + wnP*64 + ((lane&16)?8:0))*2u;
        float acc[2][8][4] = {};
        #pragma unroll
        for (int ks=0; ks<10; ks++){
            unsigned ph[2][4], pl[2][4];
            #pragma unroll
            for (int mt=0;mt<2;mt++){
                ldsm4(aPh + (unsigned)(mt*16*168 + ks*16)*2u, ph[mt]);
                ldsm4(aPl + (unsigned)(mt*16*168 + ks*16)*2u, pl[mt]);
            }
            #pragma unroll
            for (int nt2=0; nt2<4; nt2++){
                unsigned vb[4];
                ldsm4t(bV + (unsigned)(ks*16*264 + nt2*16)*2u, vb);
                #pragma unroll
                for (int mt=0;mt<2;mt++){
                    mma16816(acc[mt][2*nt2],   ph[mt], vb[0], vb[1]);
                    mma16816(acc[mt][2*nt2],   pl[mt], vb[0], vb[1]);
                    mma16816(acc[mt][2*nt2+1], ph[mt], vb[2], vb[3]);
                    mma16816(acc[mt][2*nt2+1], pl[mt], vb[2], vb[3]);
                }
            }
        }
        __half* Ow = gOh + (size_t)t*WA*D;
        #pragma unroll
        for (int mt=0;mt<2;mt++){
            #pragma unroll
            for (int nt=0;nt<8;nt++){
                int q  = wmP*32 + mt*16 + (lane>>2);
                int d0 = wnP*64 + nt*8 + (lane&3)*2;
                if (q < 49){
                    Ow[d0*49+q]     = __float2half_rn(acc[mt][nt][0]);
                    Ow[(d0+1)*49+q] = __float2half_rn(acc[mt][nt][1]);
                }
                if (q+8 < 49){
                    Ow[d0*49+q+8]     = __float2half_rn(acc[mt][nt][2]);
                    Ow[(d0+1)*49+q+8] = __float2half_rn(acc[mt][nt][3]);
                }
            }
        }
    }
}

extern "C" void kernel_launch(void* const* d_in, const int* in_sizes, int n_in,
                              void* d_out, int out_size)
{
    const float* x    = (const float*)d_in[0];
    const float* mask = (const float*)d_in[1];
    const float* Wq = (const float*)d_in[2]; const float* bq = (const float*)d_in[3];
    const float* Wk = (const float*)d_in[4]; const float* bk = (const float*)d_in[5];
    const float* Wv = (const float*)d_in[6]; const float* bv = (const float*)d_in[7];
    const float* Wp = (const float*)d_in[8]; const float* bp = (const float*)d_in[9];
    float* out = (float*)d_out;

    cudaFuncSetAttribute(attn_kernel, cudaFuncAttributeMaxDynamicSharedMemorySize, SMEM_BYTES);
    cudaFuncSetAttribute((gemm128b<0,0>), cudaFuncAttributeMaxDynamicSharedMemorySize, SM_G1);
    cudaFuncSetAttribute((gemm128b<1,0>), cudaFuncAttributeMaxDynamicSharedMemorySize, SM_G1);
    cudaFuncSetAttribute((gemm128b<2,1>), cudaFuncAttributeMaxDynamicSharedMemorySize, SM_G1);

    prep_weights<<<256,256>>>(Wq, Wk, Wv, Wp);
    gemm128b<0,0><<<dim3(2,784), 256, SM_G1>>>(CIN, x + (size_t)3*TW*WA*CIN, bq, nullptr, nullptr);
    gemm128b<1,0><<<dim3(4,2352), 256, SM_G1>>>(CIN, x, bk, bv, nullptr);
    attn_kernel<<<TW, 256, SMEM_BYTES>>>(mask);
    gemm128b<2,1><<<dim3(2,784), 256, SM_G1>>>(D, nullptr, bp, nullptr, out);
}

// round 17
// speedup vs baseline: 1.4084x; 1.1101x over previous
#include <cuda_runtime.h>
#include <cuda_fp16.h>
#include <cstdint>

#define TW 2048
#define WA 49
#define NQ (TW*WA)
#define NKV (3*TW*WA)
#define CIN 512
#define D 256
#define SCALE_F 0.17677669529663687f

__device__ __half gWq_h[D*CIN];
__device__ __half gWkv_h[2*D*CIN];
__device__ __half gWp_h[D*D];
__device__ __half gQh[(size_t)NQ*D];
__device__ __half gK[(size_t)NKV*D], gV[(size_t)NKV*D];
__device__ __half gOh[(size_t)NQ*D];

__device__ __forceinline__ void fsplit(float v, __half& hi, __half& lo){
    hi = __float2half_rn(v);
    lo = __float2half_rn(v - __half2float(hi));
}

__device__ __forceinline__ void mma16816(float c[4], const unsigned a[4], unsigned b0, unsigned b1){
    asm volatile(
      "mma.sync.aligned.m16n8k16.row.col.f32.f16.f16.f32 "
      "{%0,%1,%2,%3},{%4,%5,%6,%7},{%8,%9},{%0,%1,%2,%3};\n"
      : "+f"(c[0]), "+f"(c[1]), "+f"(c[2]), "+f"(c[3])
      : "r"(a[0]), "r"(a[1]), "r"(a[2]), "r"(a[3]), "r"(b0), "r"(b1));
}

__device__ __forceinline__ void ldsm4(unsigned addr, unsigned r[4]){
    asm volatile("ldmatrix.sync.aligned.m8n8.x4.shared.b16 {%0,%1,%2,%3}, [%4];\n"
      : "=r"(r[0]), "=r"(r[1]), "=r"(r[2]), "=r"(r[3]) : "r"(addr));
}
__device__ __forceinline__ void ldsm4t(unsigned addr, unsigned r[4]){
    asm volatile("ldmatrix.sync.aligned.m8n8.x4.trans.shared.b16 {%0,%1,%2,%3}, [%4];\n"
      : "=r"(r[0]), "=r"(r[1]), "=r"(r[2]), "=r"(r[3]) : "r"(addr));
}
__device__ __forceinline__ void cpa16(unsigned dst, const void* src){
    asm volatile("cp.async.cg.shared.global [%0], [%1], 16;\n" :: "r"(dst), "l"(src) : "memory");
}
__device__ __forceinline__ void cpa4(unsigned dst, const void* src){
    asm volatile("cp.async.ca.shared.global [%0], [%1], 4;\n" :: "r"(dst), "l"(src) : "memory");
}
#define CP_COMMIT()  asm volatile("cp.async.commit_group;\n" ::: "memory")
#define CP_WAIT0()   asm volatile("cp.async.wait_group 0;\n" ::: "memory")
#define CP_WAIT1()   asm volatile("cp.async.wait_group 1;\n" ::: "memory")

__global__ void prep_weights(const float* __restrict__ Wq, const float* __restrict__ Wk,
                             const float* __restrict__ Wv, const float* __restrict__ Wp){
    int i0 = blockIdx.x*blockDim.x + threadIdx.x, st = gridDim.x*blockDim.x;
    for (int i=i0; i<D*CIN; i+=st){ int n=i/CIN, k=i%CIN; gWq_h[i] = __float2half_rn(Wq[k*D+n]); }
    for (int i=i0; i<2*D*CIN; i+=st){ int n=i/CIN, k=i%CIN;
        float v = (n<D) ? Wk[k*D+n] : Wv[k*D+n-D]; gWkv_h[i] = __float2half_rn(v); }
    for (int i=i0; i<D*D; i+=st){ int n=i/D, k=i%D; gWp_h[i] = __float2half_rn(Wp[k*D+n]); }
}

// ------- 128x128 tile GEMM, k-slab 64, dbl-buffered, 2 CTAs/SM -------
// EPI 0: Q proj (A fp32)  1: K|V proj (A fp32)  2: out proj (A fp16 = gOh via cp.async)
// warps 2x4: wm = warp>>2 (2 x 64 rows), wn = warp&3 (4 x 32 cols)
// smem halves: sA 2x9216 @0 | sB 2x9216 @18432  (73728 B total)
#define ASTR 72
#define ABUF 9216
template<int EPI, int AHALF>
__global__ __launch_bounds__(256,2)
void gemm128b(int KT, const float* __restrict__ A,
              const float* __restrict__ bias0, const float* __restrict__ bias1,
              float* __restrict__ outF)
{
    extern __shared__ __half smh[];
    const int tid = threadIdx.x, lane = tid&31, warp = tid>>5;
    const int wm = warp>>2, wn = warp&3;
    const int m0 = blockIdx.y*128, n0 = blockIdx.x*128;
    const __half* Bg = (EPI==0)?gWq_h:(EPI==1)?gWkv_h:gWp_h;

    // fp32-A staging (per 32-col half): 128r x 32c = 1024 float4, 4/thread
    const int arA[4] = { (tid)>>3, (tid+256)>>3, (tid+512)>>3, (tid+768)>>3 };
    const int acA    = (tid&7)<<2;
    // fp16 staging (B; A when AHALF): 128r x 64c = 1024 x 16B chunks, 4/thread
    const int brB[4] = { tid>>3, (tid>>3)+32, (tid>>3)+64, (tid>>3)+96 };
    const int bcB    = (tid&7)<<3;   // halves offset of 16B chunk

    const unsigned smb = (unsigned)__cvta_generic_to_shared(smh);
    const int aoff = (wm*64 + (lane&15))*ASTR + ((lane&16)?8:0);
    const int boff = (wn*32 + (lane&7) + ((lane&16)?8:0))*ASTR + ((lane&8)?8:0);

    float acc[4][4][4] = {};
    float4 pa[4];

    const int NS = KT >> 6;

    // ---- prologue: slab 0 ----
    #pragma unroll
    for (int i=0;i<4;i++)
        cpa16(smb + (18432u + (unsigned)(brB[i]*ASTR + bcB))*2u,
              Bg + (size_t)(n0+brB[i])*KT + bcB);
    if (AHALF){
        #pragma unroll
        for (int i=0;i<4;i++)
            cpa16(smb + (unsigned)(brB[i]*ASTR + bcB)*2u,
                  gOh + (size_t)(m0+brB[i])*KT + bcB);
        CP_COMMIT();
    } else {
        CP_COMMIT();
        #pragma unroll
        for (int h=0;h<2;h++){
            #pragma unroll
            for (int i=0;i<4;i++) pa[i] = *(const float4*)(A + (size_t)(m0+arA[i])*KT + h*32 + acA);
            #pragma unroll
            for (int i=0;i<4;i++){
                int o = arA[i]*ASTR + h*32 + acA;
                __half h0,h1,h2,h3,l0,l1,l2,l3;
                fsplit(pa[i].x,h0,l0); fsplit(pa[i].y,h1,l1);
                fsplit(pa[i].z,h2,l2); fsplit(pa[i].w,h3,l3);
                *(__half2*)&smh[o]   = __halves2half2(h0,h1);
                *(__half2*)&smh[o+2] = __halves2half2(h2,h3);
            }
        }
    }

    for (int s=0; s<NS; s++){
        const int buf = s&1, nb = buf^1;
        const bool more = (s+1 < NS);
        const int kk = (s+1)<<6;
        if (more){
            #pragma unroll
            for (int i=0;i<4;i++)
                cpa16(smb + (18432u + (unsigned)(nb*ABUF + brB[i]*ASTR + bcB))*2u,
                      Bg + (size_t)(n0+brB[i])*KT + kk + bcB);
            if (AHALF){
                #pragma unroll
                for (int i=0;i<4;i++)
                    cpa16(smb + (unsigned)(nb*ABUF + brB[i]*ASTR + bcB)*2u,
                          gOh + (size_t)(m0+brB[i])*KT + kk + bcB);
            }
            CP_COMMIT();
            if (!AHALF){
                #pragma unroll
                for (int i=0;i<4;i++) pa[i] = *(const float4*)(A + (size_t)(m0+arA[i])*KT + kk + acA);
            }
            CP_WAIT1();
        } else {
            CP_WAIT0();
        }
        __syncthreads();

        const unsigned aH = smb + (unsigned)(buf*ABUF + aoff)*2u;
        const unsigned bB = smb + (unsigned)(18432 + buf*ABUF + boff)*2u;

        // ks = 0,1
        #pragma unroll
        for (int ks=0; ks<2; ks++){
            unsigned ah[4][4];
            #pragma unroll
            for (int mt=0;mt<4;mt++)
                ldsm4(aH + (unsigned)(mt*16*ASTR + ks*16)*2u, ah[mt]);
            #pragma unroll
            for (int nt2=0; nt2<2; nt2++){
                unsigned bb[4];
                ldsm4(bB + (unsigned)(nt2*16*ASTR + ks*16)*2u, bb);
                #pragma unroll
                for (int mt=0;mt<4;mt++){
                    mma16816(acc[mt][2*nt2],   ah[mt], bb[0], bb[1]);
                    mma16816(acc[mt][2*nt2+1], ah[mt], bb[2], bb[3]);
                }
            }
        }
        // stagger: store half-1, fetch half-2 (register reuse)
        if (more && !AHALF){
            #pragma unroll
            for (int i=0;i<4;i++){
                int o = nb*ABUF + arA[i]*ASTR + acA;
                __half h0,h1,h2,h3,l0,l1,l2,l3;
                fsplit(pa[i].x,h0,l0); fsplit(pa[i].y,h1,l1);
                fsplit(pa[i].z,h2,l2); fsplit(pa[i].w,h3,l3);
                *(__half2*)&smh[o]   = __halves2half2(h0,h1);
                *(__half2*)&smh[o+2] = __halves2half2(h2,h3);
            }
            #pragma unroll
            for (int i=0;i<4;i++) pa[i] = *(const float4*)(A + (size_t)(m0+arA[i])*KT + kk + 32 + acA);
        }
        // ks = 2,3
        #pragma unroll
        for (int ks=2; ks<4; ks++){
            unsigned ah[4][4];
            #pragma unroll
            for (int mt=0;mt<4;mt++)
                ldsm4(aH + (unsigned)(mt*16*ASTR + ks*16)*2u, ah[mt]);
            #pragma unroll
            for (int nt2=0; nt2<2; nt2++){
                unsigned bb[4];
                ldsm4(bB + (unsigned)(nt2*16*ASTR + ks*16)*2u, bb);
                #pragma unroll
                for (int mt=0;mt<4;mt++){
                    mma16816(acc[mt][2*nt2],   ah[mt], bb[0], bb[1]);
                    mma16816(acc[mt][2*nt2+1], ah[mt], bb[2], bb[3]);
                }
            }
        }
        if (more && !AHALF){
            #pragma unroll
            for (int i=0;i<4;i++){
                int o = nb*ABUF + arA[i]*ASTR + 32 + acA;
                __half h0,h1,h2,h3,l0,l1,l2,l3;
                fsplit(pa[i].x,h0,l0); fsplit(pa[i].y,h1,l1);
                fsplit(pa[i].z,h2,l2); fsplit(pa[i].w,h3,l3);
                *(__half2*)&smh[o]   = __halves2half2(h0,h1);
                *(__half2*)&smh[o+2] = __halves2half2(h2,h3);
            }
        }
        __syncthreads();
    }

    #pragma unroll
    for (int mt=0;mt<4;mt++){
        #pragma unroll
        for (int nt=0;nt<4;nt++){
            int r = m0 + wm*64 + mt*16 + (lane>>2);
            int c = n0 + wn*32 + nt*8 + (lane&3)*2;
            float v00=acc[mt][nt][0], v01=acc[mt][nt][1];
            float v10=acc[mt][nt][2], v11=acc[mt][nt][3];
            if (EPI == 0){
                float b0=bias0[c], b1=bias0[c+1];
                *(__half2*)&gQh[(size_t)r*D+c]     = __floats2half2_rn(v00+b0, v01+b1);
                *(__half2*)&gQh[(size_t)(r+8)*D+c] = __floats2half2_rn(v10+b0, v11+b1);
            } else if (EPI == 1){
                bool isV = (c >= D);
                __half* dst = isV ? gV : gK;
                const float* bb = isV ? bias1 : bias0;
                int cc = c & (D-1);
                float b0=bb[cc], b1=bb[cc+1];
                *(__half2*)&dst[(size_t)r*D+cc]     = __floats2half2_rn(v00+b0, v01+b1);
                *(__half2*)&dst[(size_t)(r+8)*D+cc] = __floats2half2_rn(v10+b0, v11+b1);
            } else {
                float b0=bias0[c], b1=bias0[c+1];
                outF[(size_t)r*D+c]       = v00+b0;
                outF[(size_t)r*D+c+1]     = v01+b1;
                outF[(size_t)(r+8)*D+c]   = v10+b0;
                outF[(size_t)(r+8)*D+c+1] = v11+b1;
            }
        }
    }
}
#define SM_G1 73728

// ---------------- attention (single-fp16 P; fp16 O store) ----------------
#define OFF_KV 55296u
#define OFF_S  139776u
#define OFF_M  180736u
#define SMEM_BYTES 190464
__global__ __launch_bounds__(256)
void attn_kernel(const float* __restrict__ mask)
{
    extern __shared__ char sm[];
    __half* sKV = (__half*)(sm + OFF_KV);
    float*  sS  = (float*)(sm + OFF_S);
    float*  sM  = (float*)(sm + OFF_M);
    __half* sPh = (__half*)sm;

    const int tid = threadIdx.x, lane = tid&31, warp = tid>>5;
    const int t = blockIdx.x;
    const size_t qb = (size_t)t*WA*D, kvb = (size_t)t*3*WA*D;
    const unsigned smb = (unsigned)__cvta_generic_to_shared(sm);

    for (int i=tid; i<49*32; i+=256){ int r=i>>5, g=(i&31)<<3;
        cpa16(smb + (unsigned)(r*264+g)*2u, gQh + qb + (size_t)r*D + g); }
    for (int i=tid; i<147*32; i+=256){ int r=i>>5, g=(i&31)<<3;
        cpa16(smb + OFF_KV + (unsigned)(r*264+g)*2u, gK + kvb + (size_t)r*D + g); }
    CP_COMMIT();
    for (int i=tid; i<WA*WA; i+=256)
        cpa4(smb + OFF_M + (unsigned)i*4u, mask + (size_t)(t&63)*WA*WA + i);
    CP_COMMIT();
    for (int i=tid; i<13*33; i+=256){ int r=147 + i/33, c=(i%33)*8;
        *(uint4*)&sKV[r*264+c] = make_uint4(0,0,0,0); }
    CP_WAIT1();
    __syncthreads();

    {
        const int wmS = warp>>1, wnS = warp&1;
        const unsigned aQ = smb + (unsigned)((wmS*16 + (lane&15))*264 + ((lane&16)?8:0))*2u;
        const unsigned bK = smb + OFF_KV
            + (unsigned)((wnS*80 + (lane&7) + ((lane&16)?8:0))*264 + ((lane&8)?8:0))*2u;
        float acc[10][4] = {};
        #pragma unroll
        for (int ks=0; ks<16; ks++){
            unsigned ah[4];
            ldsm4(aQ + ks*32u, ah);
            #pragma unroll
            for (int nt2=0; nt2<5; nt2++){
                unsigned bb[4];
                ldsm4(bK + (unsigned)(nt2*16*264)*2u + ks*32u, bb);
                mma16816(acc[2*nt2],   ah, bb[0], bb[1]);
                mma16816(acc[2*nt2+1], ah, bb[2], bb[3]);
            }
        }
        #pragma unroll
        for (int j=0;j<10;j++){
            int r = wmS*16 + (lane>>2), c = (wnS*10+j)*8 + (lane&3)*2;
            sS[r*160+c]=acc[j][0]; sS[r*160+c+1]=acc[j][1];
            sS[(r+8)*160+c]=acc[j][2]; sS[(r+8)*160+c+1]=acc[j][3];
        }
    }
    CP_WAIT0();
    __syncthreads();

    for (int i=tid; i<147*32; i+=256){ int r=i>>5, g=(i&31)<<3;
        cpa16(smb + OFF_KV + (unsigned)(r*264+g)*2u, gV + kvb + (size_t)r*D + g); }
    CP_COMMIT();

    for (int r=warp; r<49; r+=8){
        float vals[5]; float mx = -1e30f;
        #pragma unroll
        for (int i=0;i<5;i++){ int c = lane + 32*i; float v = -1e30f;
            if (c < 147){ int cm = (c>=98)?c-98:(c>=49)?c-49:c;
                v = sS[r*160+c]*SCALE_F + sM[r*49+cm]; }
            vals[i]=v; mx=fmaxf(mx,v); }
        #pragma unroll
        for (int o=16;o;o>>=1) mx = fmaxf(mx, __shfl_xor_sync(0xffffffffu, mx, o));
        float s = 0.f;
        #pragma unroll
        for (int i=0;i<5;i++){ int c = lane + 32*i;
            float e = (c<147) ? __expf(vals[i]-mx) : 0.f; vals[i]=e; s+=e; }
        #pragma unroll
        for (int o=16;o;o>>=1) s += __shfl_xor_sync(0xffffffffu, s, o);
        float inv = 1.f/s;
        #pragma unroll
        for (int i=0;i<5;i++){ int c = lane + 32*i;
            sPh[r*168+c] = __float2half_rn(vals[i]*inv); }
    }
    for (int i=tid; i<15*21; i+=256){ int r=49 + i/21, c=(i%21)*8;
        *(uint4*)&sPh[r*168+c] = make_uint4(0,0,0,0); }
    CP_WAIT0();
    __syncthreads();

    {
        const int wmP = warp&1, wnP = warp>>1;
        const unsigned aPh = smb + (unsigned)((wmP*32 + (lane&15))*168 + ((lane&16)?8:0))*2u;
        const unsigned bV  = smb + OFF_KV
            + (unsigned)((lane&15)*264 + wnP*64 + ((lane&16)?8:0))*2u;
        float acc[2][8][4] = {};
        #pragma unroll
        for (int ks=0; ks<10; ks++){
            unsigned ph[2][4];
            #pragma unroll
            for (int mt=0;mt<2;mt++)
                ldsm4(aPh + (unsigned)(mt*16*168 + ks*16)*2u, ph[mt]);
            #pragma unroll
            for (int nt2=0; nt2<4; nt2++){
                unsigned vb[4];
                ldsm4t(bV + (unsigned)(ks*16*264 + nt2*16)*2u, vb);
                #pragma unroll
                for (int mt=0;mt<2;mt++){
                    mma16816(acc[mt][2*nt2],   ph[mt], vb[0], vb[1]);
                    mma16816(acc[mt][2*nt2+1], ph[mt], vb[2], vb[3]);
                }
            }
        }
        __half* Ow = gOh + (size_t)t*WA*D;
        #pragma unroll
        for (int mt=0;mt<2;mt++){
            #pragma unroll
            for (int nt=0;nt<8;nt++){
                int q  = wmP*32 + mt*16 + (lane>>2);
                int d0 = wnP*64 + nt*8 + (lane&3)*2;
                if (q < 49){
                    Ow[d0*49+q]     = __float2half_rn(acc[mt][nt][0]);
                    Ow[(d0+1)*49+q] = __float2half_rn(acc[mt][nt][1]);
                }
                if (q+8 < 49){
                    Ow[d0*49+q+8]     = __float2half_rn(acc[mt][nt][2]);
                    Ow[(d0+1)*49+q+8] = __float2half_rn(acc[mt][nt][3]);
                }
            }
        }
    }
}

extern "C" void kernel_launch(void* const* d_in, const int* in_sizes, int n_in,
                              void* d_out, int out_size)
{
    const float* x    = (const float*)d_in[0];
    const float* mask = (const float*)d_in[1];
    const float* Wq = (const float*)d_in[2]; const float* bq = (const float*)d_in[3];
    const float* Wk = (const float*)d_in[4]; const float* bk = (const float*)d_in[5];
    const float* Wv = (const float*)d_in[6]; const float* bv = (const float*)d_in[7];
    const float* Wp = (const float*)d_in[8]; const float* bp = (const float*)d_in[9];
    float* out = (float*)d_out;

    cudaFuncSetAttribute(attn_kernel, cudaFuncAttributeMaxDynamicSharedMemorySize, SMEM_BYTES);
    cudaFuncSetAttribute((gemm128b<0,0>), cudaFuncAttributeMaxDynamicSharedMemorySize, SM_G1);
    cudaFuncSetAttribute((gemm128b<1,0>), cudaFuncAttributeMaxDynamicSharedMemorySize, SM_G1);
    cudaFuncSetAttribute((gemm128b<2,1>), cudaFuncAttributeMaxDynamicSharedMemorySize, SM_G1);

    prep_weights<<<256,256>>>(Wq, Wk, Wv, Wp);
    gemm128b<0,0><<<dim3(2,784), 256, SM_G1>>>(CIN, x + (size_t)3*TW*WA*CIN, bq, nullptr, nullptr);
    gemm128b<1,0><<<dim3(4,2352), 256, SM_G1>>>(CIN, x, bk, bv, nullptr);
    attn_kernel<<<TW, 256, SMEM_BYTES>>>(mask);
    gemm128b<2,1><<<dim3(2,784), 256, SM_G1>>>(D, nullptr, bp, nullptr, out);
}